// round 1
// baseline (speedup 1.0000x reference)
#include <cuda_runtime.h>
#include <cstdint>

// Problem constants
#define NROWS 65536          // N = 4096*16
#define TTRAJ 8
// Output layout (floats), concatenated: traj, mu, logvar, prob_list
#define TRAJ_T_STRIDE 4194304ull   // 16*65536*4
#define TRAJ_H_STRIDE 262144ull    // 65536*4
#define MU_OFF   33554432ull
#define LV_OFF   35651584ull
#define PROB_OFF 37748736ull

// scratch: per-row mu[32] then std[32]
static __device__ __align__(16) float g_musig[NROWS * 64];

// ---------------- packed f32x2 helpers ----------------
__device__ __forceinline__ unsigned long long pk2(float a, float b) {
    unsigned long long r;
    asm("mov.b64 %0, {%1, %2};" : "=l"(r) : "f"(a), "f"(b));
    return r;
}
__device__ __forceinline__ float2 upk(unsigned long long v) {
    float2 r;
    asm("mov.b64 {%0, %1}, %2;" : "=f"(r.x), "=f"(r.y) : "l"(v));
    return r;
}
__device__ __forceinline__ unsigned long long ffma2(unsigned long long a,
                                                    unsigned long long b,
                                                    unsigned long long c) {
    unsigned long long d;
    asm("fma.rn.f32x2 %0, %1, %2, %3;" : "=l"(d) : "l"(a), "l"(b), "l"(c));
    return d;
}

// ---------------- JAX threefry2x32, key = (0,1) ----------------
// partitionable scheme (JAX >= 0.4.36 default): bits[i] = o0 ^ o1 of
// threefry2x32(key, (hi32(i)=0, lo32(i)=i))
__device__ __forceinline__ uint32_t rotl32(uint32_t x, int r) {
    return __funnelshift_l(x, x, r);
}
__device__ __forceinline__ uint32_t tf_bits(uint32_t c) {
    const uint32_t ks2 = 0x1BD11BDBu;  // 0 ^ 1 ^ 0x1BD11BDA
    uint32_t x0 = 0u;        // counter_hi + ks0(=0)
    uint32_t x1 = c + 1u;    // counter_lo + ks1(=1)
    // block 1: rotations {13,15,26,6}
    x0 += x1; x1 = rotl32(x1, 13); x1 ^= x0;
    x0 += x1; x1 = rotl32(x1, 15); x1 ^= x0;
    x0 += x1; x1 = rotl32(x1, 26); x1 ^= x0;
    x0 += x1; x1 = rotl32(x1, 6);  x1 ^= x0;
    x0 += 1u;            x1 += ks2 + 1u;
    // block 2: {17,29,16,24}
    x0 += x1; x1 = rotl32(x1, 17); x1 ^= x0;
    x0 += x1; x1 = rotl32(x1, 29); x1 ^= x0;
    x0 += x1; x1 = rotl32(x1, 16); x1 ^= x0;
    x0 += x1; x1 = rotl32(x1, 24); x1 ^= x0;
    x0 += ks2;           x1 += 2u;
    // block 3: {13,15,26,6}
    x0 += x1; x1 = rotl32(x1, 13); x1 ^= x0;
    x0 += x1; x1 = rotl32(x1, 15); x1 ^= x0;
    x0 += x1; x1 = rotl32(x1, 26); x1 ^= x0;
    x0 += x1; x1 = rotl32(x1, 6);  x1 ^= x0;
    x0 += 0u;            x1 += 1u + 3u;
    // block 4: {17,29,16,24}
    x0 += x1; x1 = rotl32(x1, 17); x1 ^= x0;
    x0 += x1; x1 = rotl32(x1, 29); x1 ^= x0;
    x0 += x1; x1 = rotl32(x1, 16); x1 ^= x0;
    x0 += x1; x1 = rotl32(x1, 24); x1 ^= x0;
    x0 += 1u;            x1 += ks2 + 4u;
    // block 5: {13,15,26,6}
    x0 += x1; x1 = rotl32(x1, 13); x1 ^= x0;
    x0 += x1; x1 = rotl32(x1, 15); x1 ^= x0;
    x0 += x1; x1 = rotl32(x1, 26); x1 ^= x0;
    x0 += x1; x1 = rotl32(x1, 6);  x1 ^= x0;
    x0 += ks2;           x1 += 5u;
    return x0 ^ x1;
}

// XLA ErfInv f32 (Giles polynomial) — matches lax.erf_inv closely
__device__ __forceinline__ float erfinv_xla(float x) {
    float w = -log1pf(-x * x);
    float p;
    if (w < 5.0f) {
        w -= 2.5f;
        p = 2.81022636e-08f;
        p = fmaf(p, w, 3.43273939e-07f);
        p = fmaf(p, w, -3.5233877e-06f);
        p = fmaf(p, w, -4.39150654e-06f);
        p = fmaf(p, w, 0.00021858087f);
        p = fmaf(p, w, -0.00125372503f);
        p = fmaf(p, w, -0.00417768164f);
        p = fmaf(p, w, 0.246640727f);
        p = fmaf(p, w, 1.50140941f);
    } else {
        w = sqrtf(w) - 3.0f;
        p = -0.000200214257f;
        p = fmaf(p, w, 0.000100950558f);
        p = fmaf(p, w, 0.00134934322f);
        p = fmaf(p, w, -0.00367342844f);
        p = fmaf(p, w, 0.00573950773f);
        p = fmaf(p, w, -0.0076224613f);
        p = fmaf(p, w, 0.00943887047f);
        p = fmaf(p, w, 1.00167406f);
        p = fmaf(p, w, 2.83297682f);
    }
    return p * x;
}

// bits -> N(0,1) sample, exactly as jax.random.normal(float32)
__device__ __forceinline__ float bits_to_normal(uint32_t b) {
    const float U_LO = -0.99999994f;   // nextafter(-1, 0)
    float f = __uint_as_float((b >> 9) | 0x3f800000u) - 1.0f;   // [0,1)
    float u = f * 2.0f + U_LO;          // (maxval-minval) rounds to 2.0f
    u = fmaxf(u, U_LO);
    return 1.41421356237f * erfinv_xla(u);   // f32(sqrt(2)) = 0x3FB504F3
}

// ======================= encoder =======================
// one thread per row n: x[64] -> h1[60] -> mu[32], logvar[32]
__global__ __launch_bounds__(256) void enc_kernel(
    const float* __restrict__ x_in,
    const float* __restrict__ e1w, const float* __restrict__ e1b,
    const float* __restrict__ mw,  const float* __restrict__ mb,
    const float* __restrict__ sw,  const float* __restrict__ sb,
    float* __restrict__ out)
{
    __shared__ __align__(16) float e1t[64 * 60];   // [l][h]
    __shared__ __align__(16) float mwt[60 * 32];   // [h][m]
    __shared__ __align__(16) float swt[60 * 32];   // [h][m]
    __shared__ __align__(16) float e1bs[60];
    __shared__ __align__(16) float mbs[32];
    __shared__ __align__(16) float sbs[32];

    int tid = threadIdx.x;
    for (int idx = tid; idx < 60 * 64; idx += 256) {
        int h = idx >> 6, l = idx & 63;
        e1t[l * 60 + h] = e1w[idx];
    }
    for (int idx = tid; idx < 32 * 60; idx += 256) {
        int m = idx / 60, h = idx - m * 60;
        mwt[h * 32 + m] = mw[idx];
        swt[h * 32 + m] = sw[idx];
    }
    if (tid < 60) e1bs[tid] = e1b[tid];
    if (tid < 32) { mbs[tid] = mb[tid]; sbs[tid] = sb[tid]; }
    __syncthreads();

    int n = blockIdx.x * 256 + tid;

    unsigned long long h1a[30];
#pragma unroll
    for (int j = 0; j < 30; j++) {
        float2 b2 = *(const float2*)&e1bs[2 * j];
        h1a[j] = pk2(b2.x, b2.y);
    }
    const float4* xr = (const float4*)(x_in + (size_t)n * 64);
#pragma unroll
    for (int q = 0; q < 16; q++) {
        float4 xv = xr[q];
        float xs[4] = {xv.x, xv.y, xv.z, xv.w};
#pragma unroll
        for (int s = 0; s < 4; s++) {
            unsigned long long xb = pk2(xs[s], xs[s]);
            const ulonglong2* wr = (const ulonglong2*)&e1t[(q * 4 + s) * 60];
#pragma unroll
            for (int j = 0; j < 15; j++) {
                ulonglong2 wv = wr[j];
                h1a[2 * j]     = ffma2(wv.x, xb, h1a[2 * j]);
                h1a[2 * j + 1] = ffma2(wv.y, xb, h1a[2 * j + 1]);
            }
        }
    }
    float h1f[60];
#pragma unroll
    for (int j = 0; j < 30; j++) {
        float2 v = upk(h1a[j]);
        h1f[2 * j]     = fmaxf(v.x, 0.0f);
        h1f[2 * j + 1] = fmaxf(v.y, 0.0f);
    }

    unsigned long long mua[16], lva[16];
#pragma unroll
    for (int j = 0; j < 16; j++) {
        float2 b2 = *(const float2*)&mbs[2 * j];
        float2 c2 = *(const float2*)&sbs[2 * j];
        mua[j] = pk2(b2.x, b2.y);
        lva[j] = pk2(c2.x, c2.y);
    }
#pragma unroll
    for (int h = 0; h < 60; h++) {
        unsigned long long hb = pk2(h1f[h], h1f[h]);
        const ulonglong2* mr = (const ulonglong2*)&mwt[h * 32];
        const ulonglong2* sr = (const ulonglong2*)&swt[h * 32];
#pragma unroll
        for (int j = 0; j < 8; j++) {
            ulonglong2 mv = mr[j];
            mua[2 * j]     = ffma2(mv.x, hb, mua[2 * j]);
            mua[2 * j + 1] = ffma2(mv.y, hb, mua[2 * j + 1]);
            ulonglong2 sv = sr[j];
            lva[2 * j]     = ffma2(sv.x, hb, lva[2 * j]);
            lva[2 * j + 1] = ffma2(sv.y, hb, lva[2 * j + 1]);
        }
    }

    float2* mo = (float2*)(out + MU_OFF) + (size_t)n * 16;
    float2* vo = (float2*)(out + LV_OFF) + (size_t)n * 16;
    float2* gm = (float2*)(g_musig + (size_t)n * 64);
#pragma unroll
    for (int j = 0; j < 16; j++) {
        float2 m = upk(mua[j]);
        float2 v = upk(lva[j]);
        mo[j] = m;
        vo[j] = v;
        gm[j] = m;
        gm[16 + j] = make_float2(expf(0.5f * v.x), expf(0.5f * v.y));
    }
}

// ======================= decoder =======================
// one thread per (n, t): eps[32] -> z[32] -> h3[60] -> out[64] + prob const
__global__ __launch_bounds__(256) void dec_kernel(
    const float* __restrict__ d1w, const float* __restrict__ d1b,
    const float* __restrict__ d2w, const float* __restrict__ d2b,
    float* __restrict__ out)
{
    __shared__ __align__(16) float d1t[32 * 60];   // [l][h]
    __shared__ __align__(16) float d2t[60 * 64];   // [h][o]
    __shared__ __align__(16) float d1bs[60];
    __shared__ __align__(16) float d2bs[64];

    int tid = threadIdx.x;
    for (int idx = tid; idx < 60 * 32; idx += 256) {
        int h = idx >> 5, l = idx & 31;
        d1t[l * 60 + h] = d1w[idx];
    }
    for (int idx = tid; idx < 64 * 60; idx += 256) {
        int o = idx / 60, h = idx - o * 60;
        d2t[h * 64 + o] = d2w[idx];
    }
    if (tid < 60) d1bs[tid] = d1b[tid];
    if (tid < 64) d2bs[tid] = d2b[tid];
    __syncthreads();

    unsigned g = blockIdx.x * 256 + tid;
    int n = g & (NROWS - 1);
    int t = g >> 16;

    // ---- eps -> z ----
    float z[32];
    uint32_t c0 = ((uint32_t)t << 21) | ((uint32_t)n << 5);
    const float4* m4 = (const float4*)(g_musig + (size_t)n * 64);
#pragma unroll
    for (int q = 0; q < 8; q++) {
        float4 mu = m4[q];
        float4 sd = m4[8 + q];
        float mus[4] = {mu.x, mu.y, mu.z, mu.w};
        float sds[4] = {sd.x, sd.y, sd.z, sd.w};
#pragma unroll
        for (int s = 0; s < 4; s++) {
            int l = q * 4 + s;
            float e = bits_to_normal(tf_bits(c0 + (uint32_t)l));
            z[l] = fmaf(e, sds[s], mus[s]);   // mu + eps*std
        }
    }

    // ---- h3 = relu(dec1_w @ z + b) ----
    unsigned long long h3a[30];
#pragma unroll
    for (int j = 0; j < 30; j++) {
        float2 b2 = *(const float2*)&d1bs[2 * j];
        h3a[j] = pk2(b2.x, b2.y);
    }
#pragma unroll
    for (int l = 0; l < 32; l++) {
        unsigned long long zb = pk2(z[l], z[l]);
        const ulonglong2* wr = (const ulonglong2*)&d1t[l * 60];
#pragma unroll
        for (int j = 0; j < 15; j++) {
            ulonglong2 wv = wr[j];
            h3a[2 * j]     = ffma2(wv.x, zb, h3a[2 * j]);
            h3a[2 * j + 1] = ffma2(wv.y, zb, h3a[2 * j + 1]);
        }
    }
    float h3f[60];
#pragma unroll
    for (int j = 0; j < 30; j++) {
        float2 v = upk(h3a[j]);
        h3f[2 * j]     = fmaxf(v.x, 0.0f);
        h3f[2 * j + 1] = fmaxf(v.y, 0.0f);
    }

    // ---- o = dec2_w @ h3 + b ----
    unsigned long long oa[32];
#pragma unroll
    for (int j = 0; j < 32; j++) {
        float2 b2 = *(const float2*)&d2bs[2 * j];
        oa[j] = pk2(b2.x, b2.y);
    }
#pragma unroll
    for (int h = 0; h < 60; h++) {
        unsigned long long hb = pk2(h3f[h], h3f[h]);
        const ulonglong2* wr = (const ulonglong2*)&d2t[h * 64];
#pragma unroll
        for (int j = 0; j < 16; j++) {
            ulonglong2 wv = wr[j];
            oa[2 * j]     = ffma2(wv.x, hb, oa[2 * j]);
            oa[2 * j + 1] = ffma2(wv.y, hb, oa[2 * j + 1]);
        }
    }

    // ---- write traj[t][hi][n][0..3] ----
    float* tb = out + (size_t)t * TRAJ_T_STRIDE + (size_t)n * 4;
#pragma unroll
    for (int hi = 0; hi < 16; hi++) {
        float2 a  = upk(oa[2 * hi]);
        float2 b2 = upk(oa[2 * hi + 1]);
        *(float4*)(tb + (size_t)hi * TRAJ_H_STRIDE) = make_float4(a.x, a.y, b2.x, b2.y);
    }

    // prob_list: exp(pdf)==1.0f exactly in fp32 (pdf <= ~1.7e-13), so 1/8.
    out[PROB_OFF + ((size_t)t << 16) + (size_t)n] = 0.125f;
}

extern "C" void kernel_launch(void* const* d_in, const int* in_sizes, int n_in,
                              void* d_out, int out_size) {
    (void)in_sizes; (void)n_in; (void)out_size;
    const float* h_input = (const float*)d_in[0];
    // d_in[1] = num_traj (always 8)
    const float* e1w = (const float*)d_in[2];
    const float* e1b = (const float*)d_in[3];
    const float* mw  = (const float*)d_in[4];
    const float* mb  = (const float*)d_in[5];
    const float* sw  = (const float*)d_in[6];
    const float* sb  = (const float*)d_in[7];
    const float* d1w = (const float*)d_in[8];
    const float* d1b = (const float*)d_in[9];
    const float* d2w = (const float*)d_in[10];
    const float* d2b = (const float*)d_in[11];
    float* out = (float*)d_out;

    enc_kernel<<<NROWS / 256, 256>>>(h_input, e1w, e1b, mw, mb, sw, sb, out);
    dec_kernel<<<(NROWS * TTRAJ) / 256, 256>>>(d1w, d1b, d2w, d2b, out);
}

// round 2
// speedup vs baseline: 1.0202x; 1.0202x over previous
#include <cuda_runtime.h>
#include <cstdint>

// Problem constants
#define NROWS 65536          // N = 4096*16
#define TTRAJ 8
// Output layout (floats), concatenated: traj, mu, logvar, prob_list
#define TRAJ_T_STRIDE 4194304ull   // 16*65536*4
#define TRAJ_H_STRIDE 262144ull    // 65536*4
#define MU_OFF   33554432ull
#define LV_OFF   35651584ull
#define PROB_OFF 37748736ull

// scratch: per-row mu[32] then std[32]
static __device__ __align__(16) float g_musig[NROWS * 64];

// ---------------- packed f32x2 helpers ----------------
__device__ __forceinline__ unsigned long long pk2(float a, float b) {
    unsigned long long r;
    asm("mov.b64 %0, {%1, %2};" : "=l"(r) : "f"(a), "f"(b));
    return r;
}
__device__ __forceinline__ float2 upk(unsigned long long v) {
    float2 r;
    asm("mov.b64 {%0, %1}, %2;" : "=f"(r.x), "=f"(r.y) : "l"(v));
    return r;
}
__device__ __forceinline__ unsigned long long ffma2(unsigned long long a,
                                                    unsigned long long b,
                                                    unsigned long long c) {
    unsigned long long d;
    asm("fma.rn.f32x2 %0, %1, %2, %3;" : "=l"(d) : "l"(a), "l"(b), "l"(c));
    return d;
}

// ---------------- JAX threefry2x32, key = (0,1) ----------------
// partitionable scheme: bits[i] = o0 ^ o1 of threefry2x32(key, (0, i))
__device__ __forceinline__ uint32_t rotl32(uint32_t x, int r) {
    return __funnelshift_l(x, x, r);
}
__device__ __forceinline__ uint32_t tf_bits(uint32_t c) {
    const uint32_t ks2 = 0x1BD11BDBu;  // 0 ^ 1 ^ 0x1BD11BDA
    uint32_t x0 = 0u;        // counter_hi + ks0(=0)
    uint32_t x1 = c + 1u;    // counter_lo + ks1(=1)
    x0 += x1; x1 = rotl32(x1, 13); x1 ^= x0;
    x0 += x1; x1 = rotl32(x1, 15); x1 ^= x0;
    x0 += x1; x1 = rotl32(x1, 26); x1 ^= x0;
    x0 += x1; x1 = rotl32(x1, 6);  x1 ^= x0;
    x0 += 1u;            x1 += ks2 + 1u;
    x0 += x1; x1 = rotl32(x1, 17); x1 ^= x0;
    x0 += x1; x1 = rotl32(x1, 29); x1 ^= x0;
    x0 += x1; x1 = rotl32(x1, 16); x1 ^= x0;
    x0 += x1; x1 = rotl32(x1, 24); x1 ^= x0;
    x0 += ks2;           x1 += 2u;
    x0 += x1; x1 = rotl32(x1, 13); x1 ^= x0;
    x0 += x1; x1 = rotl32(x1, 15); x1 ^= x0;
    x0 += x1; x1 = rotl32(x1, 26); x1 ^= x0;
    x0 += x1; x1 = rotl32(x1, 6);  x1 ^= x0;
    x0 += 0u;            x1 += 1u + 3u;
    x0 += x1; x1 = rotl32(x1, 17); x1 ^= x0;
    x0 += x1; x1 = rotl32(x1, 29); x1 ^= x0;
    x0 += x1; x1 = rotl32(x1, 16); x1 ^= x0;
    x0 += x1; x1 = rotl32(x1, 24); x1 ^= x0;
    x0 += 1u;            x1 += ks2 + 4u;
    x0 += x1; x1 = rotl32(x1, 13); x1 ^= x0;
    x0 += x1; x1 = rotl32(x1, 15); x1 ^= x0;
    x0 += x1; x1 = rotl32(x1, 26); x1 ^= x0;
    x0 += x1; x1 = rotl32(x1, 6);  x1 ^= x0;
    x0 += ks2;           x1 += 5u;
    return x0 ^ x1;
}

// Branchless XLA ErfInv f32 (Giles) with fast log. Always evaluates both
// polynomial arms + select — avoids BSSY/BSYNC and divergence.
__device__ __forceinline__ float bits_to_normal(uint32_t b) {
    const float U_LO = -0.99999994f;   // nextafter(-1, 0)
    float f = __uint_as_float((b >> 9) | 0x3f800000u) - 1.0f;   // [0,1)
    float u = f * 2.0f + U_LO;
    u = fmaxf(u, U_LO);

    float w = -__logf(fmaf(-u, u, 1.0f));     // -log(1-u^2), w >= ~1e-7
    // fast arm (w < 5)
    float wf = w - 2.5f;
    float pf = 2.81022636e-08f;
    pf = fmaf(pf, wf, 3.43273939e-07f);
    pf = fmaf(pf, wf, -3.5233877e-06f);
    pf = fmaf(pf, wf, -4.39150654e-06f);
    pf = fmaf(pf, wf, 0.00021858087f);
    pf = fmaf(pf, wf, -0.00125372503f);
    pf = fmaf(pf, wf, -0.00417768164f);
    pf = fmaf(pf, wf, 0.246640727f);
    pf = fmaf(pf, wf, 1.50140941f);
    // slow arm (w >= 5)
    float ws = __fsqrt_rn(w) - 3.0f;
    float ps = -0.000200214257f;
    ps = fmaf(ps, ws, 0.000100950558f);
    ps = fmaf(ps, ws, 0.00134934322f);
    ps = fmaf(ps, ws, -0.00367342844f);
    ps = fmaf(ps, ws, 0.00573950773f);
    ps = fmaf(ps, ws, -0.0076224613f);
    ps = fmaf(ps, ws, 0.00943887047f);
    ps = fmaf(ps, ws, 1.00167406f);
    ps = fmaf(ps, ws, 2.83297682f);

    float p = (w < 5.0f) ? pf : ps;
    return 1.41421356237f * p * u;
}

// ======================= encoder =======================
// one thread per row n: x[64] -> h1[60] -> mu[32], logvar[32]
__global__ __launch_bounds__(256, 2) void enc_kernel(
    const float* __restrict__ x_in,
    const float* __restrict__ e1w, const float* __restrict__ e1b,
    const float* __restrict__ mw,  const float* __restrict__ mb,
    const float* __restrict__ sw,  const float* __restrict__ sb,
    float* __restrict__ out)
{
    __shared__ __align__(16) float e1t[64 * 60];   // [l][h]
    __shared__ __align__(16) float mwt[60 * 32];   // [h][m]
    __shared__ __align__(16) float swt[60 * 32];   // [h][m]
    __shared__ __align__(16) float e1bs[60];
    __shared__ __align__(16) float mbs[32];
    __shared__ __align__(16) float sbs[32];

    int tid = threadIdx.x;
    for (int idx = tid; idx < 60 * 64; idx += 256) {
        int h = idx >> 6, l = idx & 63;
        e1t[l * 60 + h] = e1w[idx];
    }
    for (int idx = tid; idx < 32 * 60; idx += 256) {
        int m = idx / 60, h = idx - m * 60;
        mwt[h * 32 + m] = mw[idx];
        swt[h * 32 + m] = sw[idx];
    }
    if (tid < 60) e1bs[tid] = e1b[tid];
    if (tid < 32) { mbs[tid] = mb[tid]; sbs[tid] = sb[tid]; }
    __syncthreads();

    int n = blockIdx.x * 256 + tid;

    unsigned long long h1a[30];
#pragma unroll
    for (int j = 0; j < 30; j++) {
        float2 b2 = *(const float2*)&e1bs[2 * j];
        h1a[j] = pk2(b2.x, b2.y);
    }
    const float4* xr = (const float4*)(x_in + (size_t)n * 64);
#pragma unroll
    for (int q = 0; q < 16; q++) {
        float4 xv = xr[q];
        float xs[4] = {xv.x, xv.y, xv.z, xv.w};
#pragma unroll
        for (int s = 0; s < 4; s++) {
            unsigned long long xb = pk2(xs[s], xs[s]);
            const ulonglong2* wr = (const ulonglong2*)&e1t[(q * 4 + s) * 60];
#pragma unroll
            for (int j = 0; j < 15; j++) {
                ulonglong2 wv = wr[j];
                h1a[2 * j]     = ffma2(wv.x, xb, h1a[2 * j]);
                h1a[2 * j + 1] = ffma2(wv.y, xb, h1a[2 * j + 1]);
            }
        }
    }
    float h1f[60];
#pragma unroll
    for (int j = 0; j < 30; j++) {
        float2 v = upk(h1a[j]);
        h1f[2 * j]     = fmaxf(v.x, 0.0f);
        h1f[2 * j + 1] = fmaxf(v.y, 0.0f);
    }

    float2* gm = (float2*)(g_musig + (size_t)n * 64);

    // ---- pass 1: mu ----
    {
        unsigned long long mua[16];
#pragma unroll
        for (int j = 0; j < 16; j++) {
            float2 b2 = *(const float2*)&mbs[2 * j];
            mua[j] = pk2(b2.x, b2.y);
        }
#pragma unroll
        for (int h = 0; h < 60; h++) {
            unsigned long long hb = pk2(h1f[h], h1f[h]);
            const ulonglong2* mr = (const ulonglong2*)&mwt[h * 32];
#pragma unroll
            for (int j = 0; j < 8; j++) {
                ulonglong2 mv = mr[j];
                mua[2 * j]     = ffma2(mv.x, hb, mua[2 * j]);
                mua[2 * j + 1] = ffma2(mv.y, hb, mua[2 * j + 1]);
            }
        }
        float2* mo = (float2*)(out + MU_OFF) + (size_t)n * 16;
#pragma unroll
        for (int j = 0; j < 16; j++) {
            float2 m = upk(mua[j]);
            mo[j] = m;
            gm[j] = m;
        }
    }

    // ---- pass 2: logvar ----
    {
        unsigned long long lva[16];
#pragma unroll
        for (int j = 0; j < 16; j++) {
            float2 c2 = *(const float2*)&sbs[2 * j];
            lva[j] = pk2(c2.x, c2.y);
        }
#pragma unroll
        for (int h = 0; h < 60; h++) {
            unsigned long long hb = pk2(h1f[h], h1f[h]);
            const ulonglong2* sr = (const ulonglong2*)&swt[h * 32];
#pragma unroll
            for (int j = 0; j < 8; j++) {
                ulonglong2 sv = sr[j];
                lva[2 * j]     = ffma2(sv.x, hb, lva[2 * j]);
                lva[2 * j + 1] = ffma2(sv.y, hb, lva[2 * j + 1]);
            }
        }
        float2* vo = (float2*)(out + LV_OFF) + (size_t)n * 16;
#pragma unroll
        for (int j = 0; j < 16; j++) {
            float2 v = upk(lva[j]);
            vo[j] = v;
            gm[16 + j] = make_float2(expf(0.5f * v.x), expf(0.5f * v.y));
        }
    }
}

// ======================= decoder =======================
// one thread per (n, t): eps[32] -> z[32] -> h3[60] -> out[64] (two halves)
__global__ __launch_bounds__(256, 2) void dec_kernel(
    const float* __restrict__ d1w, const float* __restrict__ d1b,
    const float* __restrict__ d2w, const float* __restrict__ d2b,
    float* __restrict__ out)
{
    __shared__ __align__(16) float d1t[32 * 60];      // [l][h]
    __shared__ __align__(16) float d2t[2 * 60 * 32];  // [half][h][o']
    __shared__ __align__(16) float d1bs[60];
    __shared__ __align__(16) float d2bs[64];

    int tid = threadIdx.x;
    for (int idx = tid; idx < 60 * 32; idx += 256) {
        int h = idx >> 5, l = idx & 31;
        d1t[l * 60 + h] = d1w[idx];
    }
    for (int idx = tid; idx < 64 * 60; idx += 256) {
        int o = idx / 60, h = idx - o * 60;
        d2t[(o >> 5) * 1920 + h * 32 + (o & 31)] = d2w[idx];
    }
    if (tid < 60) d1bs[tid] = d1b[tid];
    if (tid < 64) d2bs[tid] = d2b[tid];
    __syncthreads();

    unsigned g = blockIdx.x * 256 + tid;
    int n = g & (NROWS - 1);
    int t = g >> 16;

    float h3f[60];
    {
        // ---- eps -> z ----
        float z[32];
        uint32_t c0 = ((uint32_t)t << 21) | ((uint32_t)n << 5);
        const float4* m4 = (const float4*)(g_musig + (size_t)n * 64);
#pragma unroll
        for (int q = 0; q < 8; q++) {
            float4 mu = m4[q];
            float4 sd = m4[8 + q];
            float mus[4] = {mu.x, mu.y, mu.z, mu.w};
            float sds[4] = {sd.x, sd.y, sd.z, sd.w};
#pragma unroll
            for (int s = 0; s < 4; s++) {
                int l = q * 4 + s;
                float e = bits_to_normal(tf_bits(c0 + (uint32_t)l));
                z[l] = fmaf(e, sds[s], mus[s]);   // mu + eps*std
            }
        }

        // ---- h3 = relu(dec1_w @ z + b) ----
        unsigned long long h3a[30];
#pragma unroll
        for (int j = 0; j < 30; j++) {
            float2 b2 = *(const float2*)&d1bs[2 * j];
            h3a[j] = pk2(b2.x, b2.y);
        }
#pragma unroll
        for (int l = 0; l < 32; l++) {
            unsigned long long zb = pk2(z[l], z[l]);
            const ulonglong2* wr = (const ulonglong2*)&d1t[l * 60];
#pragma unroll
            for (int j = 0; j < 15; j++) {
                ulonglong2 wv = wr[j];
                h3a[2 * j]     = ffma2(wv.x, zb, h3a[2 * j]);
                h3a[2 * j + 1] = ffma2(wv.y, zb, h3a[2 * j + 1]);
            }
        }
#pragma unroll
        for (int j = 0; j < 30; j++) {
            float2 v = upk(h3a[j]);
            h3f[2 * j]     = fmaxf(v.x, 0.0f);
            h3f[2 * j + 1] = fmaxf(v.y, 0.0f);
        }
    }   // z, h3a dead here

    // ---- o = dec2_w @ h3 + b, in two 32-output halves (regs <= 128) ----
    float* tb = out + (size_t)t * TRAJ_T_STRIDE + (size_t)n * 4;
#pragma unroll
    for (int half = 0; half < 2; half++) {
        unsigned long long oa[16];
#pragma unroll
        for (int j = 0; j < 16; j++) {
            float2 b2 = *(const float2*)&d2bs[half * 32 + 2 * j];
            oa[j] = pk2(b2.x, b2.y);
        }
        const float* wbase = &d2t[half * 1920];
#pragma unroll
        for (int h = 0; h < 60; h++) {
            unsigned long long hb = pk2(h3f[h], h3f[h]);
            const ulonglong2* wr = (const ulonglong2*)&wbase[h * 32];
#pragma unroll
            for (int j = 0; j < 8; j++) {
                ulonglong2 wv = wr[j];
                oa[2 * j]     = ffma2(wv.x, hb, oa[2 * j]);
                oa[2 * j + 1] = ffma2(wv.y, hb, oa[2 * j + 1]);
            }
        }
#pragma unroll
        for (int jj = 0; jj < 8; jj++) {
            int hi = half * 8 + jj;
            float2 a  = upk(oa[2 * jj]);
            float2 b2 = upk(oa[2 * jj + 1]);
            *(float4*)(tb + (size_t)hi * TRAJ_H_STRIDE) =
                make_float4(a.x, a.y, b2.x, b2.y);
        }
    }

    // prob_list: exp(pdf)==1.0f exactly in fp32 (pdf <= ~1.7e-13), so 1/8.
    out[PROB_OFF + ((size_t)t << 16) + (size_t)n] = 0.125f;
}

extern "C" void kernel_launch(void* const* d_in, const int* in_sizes, int n_in,
                              void* d_out, int out_size) {
    (void)in_sizes; (void)n_in; (void)out_size;
    const float* h_input = (const float*)d_in[0];
    // d_in[1] = num_traj (always 8)
    const float* e1w = (const float*)d_in[2];
    const float* e1b = (const float*)d_in[3];
    const float* mw  = (const float*)d_in[4];
    const float* mb  = (const float*)d_in[5];
    const float* sw  = (const float*)d_in[6];
    const float* sb  = (const float*)d_in[7];
    const float* d1w = (const float*)d_in[8];
    const float* d1b = (const float*)d_in[9];
    const float* d2w = (const float*)d_in[10];
    const float* d2b = (const float*)d_in[11];
    float* out = (float*)d_out;

    enc_kernel<<<NROWS / 256, 256>>>(h_input, e1w, e1b, mw, mb, sw, sb, out);
    dec_kernel<<<(NROWS * TTRAJ) / 256, 256>>>(d1w, d1b, d2w, d2b, out);
}

// round 4
// speedup vs baseline: 1.6367x; 1.6044x over previous
#include <cuda_runtime.h>
#include <cstdint>

// Problem constants
#define NROWS 65536          // N = 4096*16
#define TTRAJ 8
// Output layout (floats), concatenated: traj, mu, logvar, prob_list
#define TRAJ_T_STRIDE 4194304ull   // 16*65536*4
#define TRAJ_H_STRIDE 262144ull    // 65536*4
#define MU_OFF   33554432ull
#define LV_OFF   35651584ull
#define PROB_OFF 37748736ull

// scratch: per-row mu[32] then std[32]
static __device__ __align__(16) float g_musig[NROWS * 64];
// transpose scratch: d2w^T (3840) + mw^T (1920) + sw^T (1920)
static __device__ __align__(16) float g_xpose[7680];

// constant weights: [0..3839]=d2w^T [h][o], [3840..5759]=mw^T [h][m],
// [5760..7679]=sw^T [h][m]
__constant__ __align__(16) float c_w[7680];

// ---------------- packed f32x2 helpers ----------------
__device__ __forceinline__ unsigned long long pk2(float a, float b) {
    unsigned long long r;
    asm("mov.b64 %0, {%1, %2};" : "=l"(r) : "f"(a), "f"(b));
    return r;
}
__device__ __forceinline__ float2 upk(unsigned long long v) {
    float2 r;
    asm("mov.b64 {%0, %1}, %2;" : "=f"(r.x), "=f"(r.y) : "l"(v));
    return r;
}
__device__ __forceinline__ unsigned long long ffma2(unsigned long long a,
                                                    unsigned long long b,
                                                    unsigned long long c) {
    unsigned long long d;
    asm("fma.rn.f32x2 %0, %1, %2, %3;" : "=l"(d) : "l"(a), "l"(b), "l"(c));
    return d;
}

// ---------------- JAX threefry2x32, key = (0,1) ----------------
__device__ __forceinline__ uint32_t rotl32(uint32_t x, int r) {
    return __funnelshift_l(x, x, r);
}
__device__ __forceinline__ uint32_t tf_bits(uint32_t c) {
    const uint32_t ks2 = 0x1BD11BDBu;
    uint32_t x0 = 0u;
    uint32_t x1 = c + 1u;
    x0 += x1; x1 = rotl32(x1, 13); x1 ^= x0;
    x0 += x1; x1 = rotl32(x1, 15); x1 ^= x0;
    x0 += x1; x1 = rotl32(x1, 26); x1 ^= x0;
    x0 += x1; x1 = rotl32(x1, 6);  x1 ^= x0;
    x0 += 1u;            x1 += ks2 + 1u;
    x0 += x1; x1 = rotl32(x1, 17); x1 ^= x0;
    x0 += x1; x1 = rotl32(x1, 29); x1 ^= x0;
    x0 += x1; x1 = rotl32(x1, 16); x1 ^= x0;
    x0 += x1; x1 = rotl32(x1, 24); x1 ^= x0;
    x0 += ks2;           x1 += 2u;
    x0 += x1; x1 = rotl32(x1, 13); x1 ^= x0;
    x0 += x1; x1 = rotl32(x1, 15); x1 ^= x0;
    x0 += x1; x1 = rotl32(x1, 26); x1 ^= x0;
    x0 += x1; x1 = rotl32(x1, 6);  x1 ^= x0;
    x0 += 0u;            x1 += 1u + 3u;
    x0 += x1; x1 = rotl32(x1, 17); x1 ^= x0;
    x0 += x1; x1 = rotl32(x1, 29); x1 ^= x0;
    x0 += x1; x1 = rotl32(x1, 16); x1 ^= x0;
    x0 += x1; x1 = rotl32(x1, 24); x1 ^= x0;
    x0 += 1u;            x1 += ks2 + 4u;
    x0 += x1; x1 = rotl32(x1, 13); x1 ^= x0;
    x0 += x1; x1 = rotl32(x1, 15); x1 ^= x0;
    x0 += x1; x1 = rotl32(x1, 26); x1 ^= x0;
    x0 += x1; x1 = rotl32(x1, 6);  x1 ^= x0;
    x0 += ks2;           x1 += 5u;
    return x0 ^ x1;
}

// Branchless XLA ErfInv f32 with fast log
__device__ __forceinline__ float bits_to_normal(uint32_t b) {
    const float U_LO = -0.99999994f;
    float f = __uint_as_float((b >> 9) | 0x3f800000u) - 1.0f;
    float u = f * 2.0f + U_LO;
    u = fmaxf(u, U_LO);

    float w = -__logf(fmaf(-u, u, 1.0f));
    float wf = w - 2.5f;
    float pf = 2.81022636e-08f;
    pf = fmaf(pf, wf, 3.43273939e-07f);
    pf = fmaf(pf, wf, -3.5233877e-06f);
    pf = fmaf(pf, wf, -4.39150654e-06f);
    pf = fmaf(pf, wf, 0.00021858087f);
    pf = fmaf(pf, wf, -0.00125372503f);
    pf = fmaf(pf, wf, -0.00417768164f);
    pf = fmaf(pf, wf, 0.246640727f);
    pf = fmaf(pf, wf, 1.50140941f);
    float ws = __fsqrt_rn(w) - 3.0f;
    float ps = -0.000200214257f;
    ps = fmaf(ps, ws, 0.000100950558f);
    ps = fmaf(ps, ws, 0.00134934322f);
    ps = fmaf(ps, ws, -0.00367342844f);
    ps = fmaf(ps, ws, 0.00573950773f);
    ps = fmaf(ps, ws, -0.0076224613f);
    ps = fmaf(ps, ws, 0.00943887047f);
    ps = fmaf(ps, ws, 1.00167406f);
    ps = fmaf(ps, ws, 2.83297682f);

    float p = (w < 5.0f) ? pf : ps;
    return 1.41421356237f * p * u;
}

// ======================= prep: transpose weights for constant bank =========
__global__ void prep_kernel(const float* __restrict__ d2w,
                            const float* __restrict__ mw,
                            const float* __restrict__ sw)
{
    int tid = blockIdx.x * 256 + threadIdx.x;
    // d2w [64][60] -> [h][o] 60x64
    for (int idx = tid; idx < 3840; idx += 512) {
        int h = idx >> 6, o = idx & 63;
        g_xpose[idx] = d2w[o * 60 + h];
    }
    // mw, sw [32][60] -> [h][m] 60x32
    for (int idx = tid; idx < 1920; idx += 512) {
        int h = idx >> 5, m = idx & 31;
        g_xpose[3840 + idx] = mw[m * 60 + h];
        g_xpose[5760 + idx] = sw[m * 60 + h];
    }
}

// ======================= encoder =======================
// one thread per row n: x[64] -> h1[60] -> mu[32], logvar[32]
// e1 weights from SMEM (LSU port), mean/std weights from constant (const port)
__global__ __launch_bounds__(256, 2) void enc_kernel(
    const float* __restrict__ x_in,
    const float* __restrict__ e1w, const float* __restrict__ e1b,
    const float* __restrict__ mb,  const float* __restrict__ sb,
    float* __restrict__ out)
{
    __shared__ __align__(16) float e1t[64 * 60];   // [l][h]
    __shared__ __align__(16) float e1bs[60];
    __shared__ __align__(16) float mbs[32];
    __shared__ __align__(16) float sbs[32];

    int tid = threadIdx.x;
    for (int idx = tid; idx < 60 * 64; idx += 256) {
        int h = idx >> 6, l = idx & 63;
        e1t[l * 60 + h] = e1w[idx];
    }
    if (tid < 60) e1bs[tid] = e1b[tid];
    if (tid < 32) { mbs[tid] = mb[tid]; sbs[tid] = sb[tid]; }
    __syncthreads();

    int n = blockIdx.x * 256 + tid;

    unsigned long long h1a[30];
#pragma unroll
    for (int j = 0; j < 30; j++) {
        float2 b2 = *(const float2*)&e1bs[2 * j];
        h1a[j] = pk2(b2.x, b2.y);
    }
    const float4* xr = (const float4*)(x_in + (size_t)n * 64);
#pragma unroll
    for (int q = 0; q < 16; q++) {
        float4 xv = xr[q];
        float xs[4] = {xv.x, xv.y, xv.z, xv.w};
#pragma unroll
        for (int s = 0; s < 4; s++) {
            unsigned long long xb = pk2(xs[s], xs[s]);
            const ulonglong2* wr = (const ulonglong2*)&e1t[(q * 4 + s) * 60];
#pragma unroll
            for (int j = 0; j < 15; j++) {
                ulonglong2 wv = wr[j];
                h1a[2 * j]     = ffma2(wv.x, xb, h1a[2 * j]);
                h1a[2 * j + 1] = ffma2(wv.y, xb, h1a[2 * j + 1]);
            }
        }
    }
    float h1f[60];
#pragma unroll
    for (int j = 0; j < 30; j++) {
        float2 v = upk(h1a[j]);
        h1f[2 * j]     = fmaxf(v.x, 0.0f);
        h1f[2 * j + 1] = fmaxf(v.y, 0.0f);
    }

    float2* gm = (float2*)(g_musig + (size_t)n * 64);

    // ---- pass 1: mu (weights via constant port) ----
    {
        unsigned long long mua[16];
#pragma unroll
        for (int j = 0; j < 16; j++) {
            float2 b2 = *(const float2*)&mbs[2 * j];
            mua[j] = pk2(b2.x, b2.y);
        }
#pragma unroll
        for (int h = 0; h < 60; h++) {
            unsigned long long hb = pk2(h1f[h], h1f[h]);
            const ulonglong2* mr = (const ulonglong2*)&c_w[3840 + h * 32];
#pragma unroll
            for (int j = 0; j < 8; j++) {
                ulonglong2 mv = mr[j];
                mua[2 * j]     = ffma2(mv.x, hb, mua[2 * j]);
                mua[2 * j + 1] = ffma2(mv.y, hb, mua[2 * j + 1]);
            }
        }
        float2* mo = (float2*)(out + MU_OFF) + (size_t)n * 16;
#pragma unroll
        for (int j = 0; j < 16; j++) {
            float2 m = upk(mua[j]);
            mo[j] = m;
            gm[j] = m;
        }
    }

    // ---- pass 2: logvar ----
    {
        unsigned long long lva[16];
#pragma unroll
        for (int j = 0; j < 16; j++) {
            float2 c2 = *(const float2*)&sbs[2 * j];
            lva[j] = pk2(c2.x, c2.y);
        }
#pragma unroll
        for (int h = 0; h < 60; h++) {
            unsigned long long hb = pk2(h1f[h], h1f[h]);
            const ulonglong2* sr = (const ulonglong2*)&c_w[5760 + h * 32];
#pragma unroll
            for (int j = 0; j < 8; j++) {
                ulonglong2 sv = sr[j];
                lva[2 * j]     = ffma2(sv.x, hb, lva[2 * j]);
                lva[2 * j + 1] = ffma2(sv.y, hb, lva[2 * j + 1]);
            }
        }
        float2* vo = (float2*)(out + LV_OFF) + (size_t)n * 16;
#pragma unroll
        for (int j = 0; j < 16; j++) {
            float2 v = upk(lva[j]);
            vo[j] = v;
            gm[16 + j] = make_float2(expf(0.5f * v.x), expf(0.5f * v.y));
        }
    }
}

// ======================= decoder =======================
// one thread per (n, t): eps[32] -> z[32] -> h3[60] -> out[64] (two halves)
// dec1 weights from SMEM (LSU port), dec2 weights from constant (const port)
__global__ __launch_bounds__(256, 2) void dec_kernel(
    const float* __restrict__ d1w, const float* __restrict__ d1b,
    const float* __restrict__ d2b,
    float* __restrict__ out)
{
    __shared__ __align__(16) float d1t[32 * 60];      // [l][h]
    __shared__ __align__(16) float d1bs[60];
    __shared__ __align__(16) float d2bs[64];

    int tid = threadIdx.x;
    for (int idx = tid; idx < 60 * 32; idx += 256) {
        int h = idx >> 5, l = idx & 31;
        d1t[l * 60 + h] = d1w[idx];
    }
    if (tid < 60) d1bs[tid] = d1b[tid];
    if (tid < 64) d2bs[tid] = d2b[tid];
    __syncthreads();

    unsigned g = blockIdx.x * 256 + tid;
    int n = g & (NROWS - 1);
    int t = g >> 16;

    float h3f[60];
    {
        // ---- eps -> z ----
        float z[32];
        uint32_t c0 = ((uint32_t)t << 21) | ((uint32_t)n << 5);
        const float4* m4 = (const float4*)(g_musig + (size_t)n * 64);
#pragma unroll
        for (int q = 0; q < 8; q++) {
            float4 mu = m4[q];
            float4 sd = m4[8 + q];
            float mus[4] = {mu.x, mu.y, mu.z, mu.w};
            float sds[4] = {sd.x, sd.y, sd.z, sd.w};
#pragma unroll
            for (int s = 0; s < 4; s++) {
                int l = q * 4 + s;
                float e = bits_to_normal(tf_bits(c0 + (uint32_t)l));
                z[l] = fmaf(e, sds[s], mus[s]);   // mu + eps*std
            }
        }

        // ---- h3 = relu(dec1_w @ z + b), weights via LSU ----
        unsigned long long h3a[30];
#pragma unroll
        for (int j = 0; j < 30; j++) {
            float2 b2 = *(const float2*)&d1bs[2 * j];
            h3a[j] = pk2(b2.x, b2.y);
        }
#pragma unroll
        for (int l = 0; l < 32; l++) {
            unsigned long long zb = pk2(z[l], z[l]);
            const ulonglong2* wr = (const ulonglong2*)&d1t[l * 60];
#pragma unroll
            for (int j = 0; j < 15; j++) {
                ulonglong2 wv = wr[j];
                h3a[2 * j]     = ffma2(wv.x, zb, h3a[2 * j]);
                h3a[2 * j + 1] = ffma2(wv.y, zb, h3a[2 * j + 1]);
            }
        }
#pragma unroll
        for (int j = 0; j < 30; j++) {
            float2 v = upk(h3a[j]);
            h3f[2 * j]     = fmaxf(v.x, 0.0f);
            h3f[2 * j + 1] = fmaxf(v.y, 0.0f);
        }
    }   // z, h3a dead here

    // ---- o = dec2_w @ h3 + b, weights via constant port, two halves ----
    float* tb = out + (size_t)t * TRAJ_T_STRIDE + (size_t)n * 4;
#pragma unroll
    for (int half = 0; half < 2; half++) {
        unsigned long long oa[16];
#pragma unroll
        for (int j = 0; j < 16; j++) {
            float2 b2 = *(const float2*)&d2bs[half * 32 + 2 * j];
            oa[j] = pk2(b2.x, b2.y);
        }
#pragma unroll
        for (int h = 0; h < 60; h++) {
            unsigned long long hb = pk2(h3f[h], h3f[h]);
            const ulonglong2* wr =
                (const ulonglong2*)&c_w[h * 64 + half * 32];
#pragma unroll
            for (int j = 0; j < 8; j++) {
                ulonglong2 wv = wr[j];
                oa[2 * j]     = ffma2(wv.x, hb, oa[2 * j]);
                oa[2 * j + 1] = ffma2(wv.y, hb, oa[2 * j + 1]);
            }
        }
#pragma unroll
        for (int jj = 0; jj < 8; jj++) {
            int hi = half * 8 + jj;
            float2 a  = upk(oa[2 * jj]);
            float2 b2 = upk(oa[2 * jj + 1]);
            *(float4*)(tb + (size_t)hi * TRAJ_H_STRIDE) =
                make_float4(a.x, a.y, b2.x, b2.y);
        }
    }

    // prob_list: exp(pdf)==1.0f exactly in fp32, so 1/8.
    out[PROB_OFF + ((size_t)t << 16) + (size_t)n] = 0.125f;
}

extern "C" void kernel_launch(void* const* d_in, const int* in_sizes, int n_in,
                              void* d_out, int out_size) {
    (void)in_sizes; (void)n_in; (void)out_size;
    const float* h_input = (const float*)d_in[0];
    const float* e1w = (const float*)d_in[2];
    const float* e1b = (const float*)d_in[3];
    const float* mw  = (const float*)d_in[4];
    const float* mb  = (const float*)d_in[5];
    const float* sw  = (const float*)d_in[6];
    const float* sb  = (const float*)d_in[7];
    const float* d1w = (const float*)d_in[8];
    const float* d1b = (const float*)d_in[9];
    const float* d2w = (const float*)d_in[10];
    const float* d2b = (const float*)d_in[11];
    float* out = (float*)d_out;

    // transpose weights on device, then D2D into constant bank (capturable)
    prep_kernel<<<2, 256>>>(d2w, mw, sw);
    void* xp_ptr = nullptr;
    cudaGetSymbolAddress(&xp_ptr, g_xpose);
    cudaMemcpyToSymbolAsync(c_w, xp_ptr, 7680 * sizeof(float), 0,
                            cudaMemcpyDeviceToDevice, 0);

    enc_kernel<<<NROWS / 256, 256>>>(h_input, e1w, e1b, mb, sb, out);
    dec_kernel<<<(NROWS * TTRAJ) / 256, 256>>>(d1w, d1b, d2b, out);
}